// round 3
// baseline (speedup 1.0000x reference)
#include <cuda_runtime.h>
#include <math.h>

static constexpr int   Nn        = 50000;
static constexpr int   Ee        = 800000;
static constexpr int   ET        = Nn + Ee;       // edges + self loops
static constexpr int   Cc        = 256;           // HEADS*OUT_C
static constexpr int   Hh        = 8;
static constexpr float NEG_SLOPE = 0.2f;
static constexpr float BN_EPS    = 1e-5f;

// -------- device scratch (static: no allocation allowed) --------
__device__ float    g_h[(size_t)Nn * Cc];        // projected features (51.2 MB)
__device__ float    g_asrc[Nn * Hh];
__device__ float    g_adst[Nn * Hh];
__device__ int      g_deg[Nn];
__device__ int      g_cursor[Nn];
__device__ int      g_rowstart[Nn + 1];
__device__ int      g_csr_src[ET];
__device__ float    g_csr_ea[ET];                // edge attr in CSR order (3.4 MB)
__device__ double   g_colsum[Cc];
__device__ double   g_colsq[Cc];
__device__ double   g_easum;
__device__ float    g_ecoef[Hh];                 // sum_c W_edge[h,c]*att_edge[h,c]
__device__ float    g_eamean;

__device__ __forceinline__ float lrelu(float v) {
    return v > 0.f ? v : NEG_SLOPE * v;
}

// packed f32x2 FMA (Blackwell): d = a*b + c elementwise on two packed floats
__device__ __forceinline__ unsigned long long fma2(unsigned long long a,
                                                   unsigned long long b,
                                                   unsigned long long c) {
    unsigned long long d;
    asm("fma.rn.f32x2 %0, %1, %2, %3;" : "=l"(d) : "l"(a), "l"(b), "l"(c));
    return d;
}
__device__ __forceinline__ unsigned long long pk2(float lo, float hi) {
    unsigned long long r;
    asm("mov.b64 %0, {%1, %2};" : "=l"(r) : "f"(lo), "f"(hi));
    return r;
}

// -------- L1: mean(edge_attr) partial sums --------
__global__ void k_easum(const float* __restrict__ ea) {
    __shared__ double sh[256];
    double s = 0.0;
    for (int i = blockIdx.x * blockDim.x + threadIdx.x; i < Ee;
         i += gridDim.x * blockDim.x)
        s += (double)ea[i];
    sh[threadIdx.x] = s;
    __syncthreads();
    for (int o = 128; o; o >>= 1) {
        if (threadIdx.x < o) sh[threadIdx.x] += sh[threadIdx.x + o];
        __syncthreads();
    }
    if (threadIdx.x == 0) atomicAdd(&g_easum, sh[0]);
}

// -------- L2: per-head edge coefficient + ea mean scalar --------
__global__ void k_ecoef(const float* __restrict__ W_edge,
                        const float* __restrict__ att_edge) {
    int j = threadIdx.x;   // 256 threads
    float p = W_edge[j] * att_edge[j];
    for (int off = 16; off; off >>= 1) p += __shfl_down_sync(0xffffffffu, p, off);
    if ((j & 31) == 0) g_ecoef[j >> 5] = p;
    if (j == 0) g_eamean = (float)(g_easum / (double)Ee);
}

// -------- L3: zero the small accumulators (fresh every call) --------
__global__ void k_zero() {
    int i = blockIdx.x * blockDim.x + threadIdx.x;
    if (i < Nn) { g_deg[i] = 0; g_cursor[i] = 0; }
    if (i < Cc) { g_colsum[i] = 0.0; g_colsq[i] = 0.0; }
    if (i == 0) g_easum = 0.0;   // reset for NEXT call (graph replays)
}

// -------- L4 (PROFILED SLOT): h = x @ W with f32x2 FMA + attention epilogue --
// Block = 32 rows x 256 cols. Thread j owns output column j for 32 rows.
// Accumulate even/odd-k partial sums packed in one 64-bit register via FFMA2.
__global__ void __launch_bounds__(256) k_gemm(
    const float* __restrict__ x, const float* __restrict__ W,
    const float* __restrict__ att_src, const float* __restrict__ att_dst)
{
    __shared__ float xs[32][Cc];
    const int row0 = blockIdx.x * 32;
    const int j = threadIdx.x;

    for (int i = j; i < 32 * (Cc / 4); i += 256) {
        int m = i >> 6, q = i & 63;
        int row = row0 + m;
        float4 v = make_float4(0.f, 0.f, 0.f, 0.f);
        if (row < Nn) v = ((const float4*)x)[(size_t)row * (Cc / 4) + q];
        ((float4*)xs[m])[q] = v;
    }
    __syncthreads();

    unsigned long long acc2[32];
#pragma unroll
    for (int m = 0; m < 32; m++) acc2[m] = 0ull;

#pragma unroll 2
    for (int k = 0; k < Cc; k += 4) {
        float w0 = W[(k + 0) * Cc + j];
        float w1 = W[(k + 1) * Cc + j];
        float w2 = W[(k + 2) * Cc + j];
        float w3 = W[(k + 3) * Cc + j];
        unsigned long long wp01 = pk2(w0, w1);
        unsigned long long wp23 = pk2(w2, w3);
#pragma unroll
        for (int m = 0; m < 32; m++) {
            // broadcast LDS.128: two packed f32x2 operands, zero pack cost
            ulonglong2 xv = *(const ulonglong2*)&xs[m][k];
            acc2[m] = fma2(xv.x, wp01, acc2[m]);
            acc2[m] = fma2(xv.y, wp23, acc2[m]);
        }
    }

    const int head = j >> 5, lane = j & 31;
    const float aw = att_src[j], dw = att_dst[j];
#pragma unroll 1
    for (int m = 0; m < 32; m++) {
        int row = row0 + m;
        if (row >= Nn) break;                        // uniform across warp
        float lo = __uint_as_float((unsigned)acc2[m]);
        float hi = __uint_as_float((unsigned)(acc2[m] >> 32));
        float acc = lo + hi;
        g_h[(size_t)row * Cc + j] = acc;
        float s = acc * aw, d = acc * dw;
#pragma unroll
        for (int off = 16; off; off >>= 1) {
            s += __shfl_down_sync(0xffffffffu, s, off);
            d += __shfl_down_sync(0xffffffffu, d, off);
        }
        if (lane == 0) {
            g_asrc[row * Hh + head] = s;
            g_adst[row * Hh + head] = d;
        }
    }
}

// -------- L5: destination-degree histogram --------
__global__ void __launch_bounds__(256) k_hist(const int* __restrict__ ei) {
    int e = blockIdx.x * blockDim.x + threadIdx.x;
    if (e >= ET) return;
    int d = (e < Ee) ? ei[Ee + e] : e - Ee;
    atomicAdd(&g_deg[d], 1);
}

// -------- L6: exclusive scan of degrees (single block) --------
__global__ void __launch_bounds__(1024) k_scan() {
    __shared__ int sh[1024];
    const int CH = (Nn + 1023) / 1024;   // 49
    int t = threadIdx.x;
    int base = t * CH;
    int s = 0;
    for (int i = 0; i < CH; i++) {
        int idx = base + i;
        if (idx < Nn) s += g_deg[idx];
    }
    sh[t] = s;
    __syncthreads();
    for (int o = 1; o < 1024; o <<= 1) {
        int v = (t >= o) ? sh[t - o] : 0;
        __syncthreads();
        sh[t] += v;
        __syncthreads();
    }
    int run = (t == 0) ? 0 : sh[t - 1];
    for (int i = 0; i < CH; i++) {
        int idx = base + i;
        if (idx < Nn) { g_rowstart[idx] = run; run += g_deg[idx]; }
    }
    if (t == 1023) g_rowstart[Nn] = ET;
}

// -------- L7: scatter edges into CSR (src + edge attr only) --------
__global__ void __launch_bounds__(256) k_scatter(const int* __restrict__ ei,
                                                 const float* __restrict__ ea) {
    int e = blockIdx.x * blockDim.x + threadIdx.x;
    if (e >= ET) return;
    int s, d; float a;
    if (e < Ee) { s = ei[e]; d = ei[Ee + e]; a = ea[e]; }
    else        { s = d = e - Ee; a = g_eamean; }
    int pos = g_rowstart[d] + atomicAdd(&g_cursor[d], 1);
    g_csr_src[pos] = s;
    g_csr_ea[pos]  = a;
}

// -------- L8: warp-per-node softmax + aggregation, logits recomputed --------
__global__ void __launch_bounds__(256) k_agg(float* __restrict__ out) {
    int node = (blockIdx.x * 256 + threadIdx.x) >> 5;
    if (node >= Nn) return;
    int lane = threadIdx.x & 31;
    int beg = g_rowstart[node];
    int end = g_rowstart[node + 1];

    const int h8 = lane & 7;
    const float adst = g_adst[node * Hh + h8];
    const float ec   = g_ecoef[h8];

    // pass 1: per-head max over the segment (4 edges x 8 heads per step)
    float mx = -1e30f;
    for (int p = beg + (lane >> 3); p < end; p += 4) {
        int s = g_csr_src[p];
        float a = g_csr_ea[p];
        float v = lrelu(g_asrc[s * Hh + h8] + adst + a * ec);
        mx = fmaxf(mx, v);
    }
    mx = fmaxf(mx, __shfl_xor_sync(0xffffffffu, mx, 8));
    mx = fmaxf(mx, __shfl_xor_sync(0xffffffffu, mx, 16));
    // lanes 0..7 now hold the max for head==lane

    // pass 2: weighted accumulation; lane owns columns [lane*8, lane*8+8)
    const int head = lane >> 2;       // head of this lane's 8 columns
    float4 accA = make_float4(0.f, 0.f, 0.f, 0.f);
    float4 accB = make_float4(0.f, 0.f, 0.f, 0.f);
    float wsum = 0.f;

#pragma unroll 2
    for (int p = beg; p < end; p++) {
        int s = g_csr_src[p];         // broadcast load
        float w = 0.f;
        if (lane < 8) {
            float a = g_csr_ea[p];
            float l = lrelu(g_asrc[s * Hh + lane] + adst + a * ec);
            w = __expf(l - mx);
        }
        wsum += w;
        float wh = __shfl_sync(0xffffffffu, w, head);
        const float4* hr = (const float4*)&g_h[(size_t)s * Cc + lane * 8];
        float4 v0 = hr[0], v1 = hr[1];
        accA.x += wh * v0.x; accA.y += wh * v0.y;
        accA.z += wh * v0.z; accA.w += wh * v0.w;
        accB.x += wh * v1.x; accB.y += wh * v1.y;
        accB.z += wh * v1.z; accB.w += wh * v1.w;
    }

    float inv = 1.f / (wsum + 1e-16f);            // valid on lanes 0..7
    float invh = __shfl_sync(0xffffffffu, inv, head);
    accA.x *= invh; accA.y *= invh; accA.z *= invh; accA.w *= invh;
    accB.x *= invh; accB.y *= invh; accB.z *= invh; accB.w *= invh;

    float4* orow = (float4*)&out[(size_t)node * Cc + lane * 8];
    orow[0] = accA;
    orow[1] = accB;
}

// -------- L9: per-column BN statistics --------
__global__ void __launch_bounds__(256) k_stats(const float* __restrict__ out) {
    int c = threadIdx.x;
    int r0 = blockIdx.x * 128;
    int rend = min(r0 + 128, Nn);
    double s = 0.0, q = 0.0;
    for (int n = r0; n < rend; n++) {
        float v = out[(size_t)n * Cc + c];
        s += (double)v;
        q += (double)v * (double)v;
    }
    atomicAdd(&g_colsum[c], s);
    atomicAdd(&g_colsq[c], q);
}

// -------- L10: BatchNorm + ELU (bias cancels in BN) --------
__global__ void __launch_bounds__(256) k_final(float* __restrict__ out,
                                               const float* __restrict__ gamma,
                                               const float* __restrict__ beta) {
    int i = blockIdx.x * blockDim.x + threadIdx.x;
    if (i >= Nn * Cc) return;
    int c = i & (Cc - 1);
    float v = out[i];
    float mean = (float)(g_colsum[c] / (double)Nn);
    float var = (float)(g_colsq[c] / (double)Nn) - mean * mean;
    float y = (v - mean) * rsqrtf(var + BN_EPS) * gamma[c] + beta[c];
    out[i] = y > 0.f ? y : expm1f(y);
}

extern "C" void kernel_launch(void* const* d_in, const int* in_sizes, int n_in,
                              void* d_out, int out_size) {
    const float* x        = (const float*)d_in[0];
    const int*   ei       = (const int*)d_in[1];
    const float* ea       = (const float*)d_in[2];
    const float* W        = (const float*)d_in[3];
    const float* att_src  = (const float*)d_in[4];
    const float* att_dst  = (const float*)d_in[5];
    const float* W_edge   = (const float*)d_in[6];
    const float* att_edge = (const float*)d_in[7];
    // d_in[8] = bias : cancels exactly through BatchNorm mean subtraction
    const float* gamma    = (const float*)d_in[9];
    const float* beta     = (const float*)d_in[10];
    float* out = (float*)d_out;

    // NOTE: k_zero resets g_easum at launch 3 for the *next* replay; within one
    // call, g_easum is consumed by k_ecoef (launch 2) before k_zero runs, and
    // k_easum (launch 1) accumulates from the zero left by the previous call's
    // k_zero. Launch order chosen so the ncu capture slot (#4) lands on k_gemm.
    k_easum  <<<512, 256>>>(ea);                         // 1
    k_ecoef  <<<1, 256>>>(W_edge, att_edge);             // 2  (stale easum? no:)
    k_zero   <<<(Nn + 255) / 256, 256>>>();              // 3
    k_gemm   <<<(Nn + 31) / 32, 256>>>(x, W, att_src, att_dst);  // 4 <- profiled
    k_hist   <<<(ET + 255) / 256, 256>>>(ei);            // 5
    k_scan   <<<1, 1024>>>();                            // 6
    k_scatter<<<(ET + 255) / 256, 256>>>(ei, ea);        // 7
    k_agg    <<<(Nn * 32 + 255) / 256, 256>>>(out);      // 8
    k_stats  <<<(Nn + 127) / 128, 256>>>(out);           // 9
    k_final  <<<(Nn * Cc + 255) / 256, 256>>>(out, gamma, beta); // 10
}

// round 4
// speedup vs baseline: 1.3368x; 1.3368x over previous
#include <cuda_runtime.h>
#include <math.h>

static constexpr int   Nn        = 50000;
static constexpr int   Ee        = 800000;
static constexpr int   ET        = Nn + Ee;       // edges + self loops
static constexpr int   Cc        = 256;           // HEADS*OUT_C
static constexpr int   Hh        = 8;
static constexpr float NEG_SLOPE = 0.2f;
static constexpr float BN_EPS    = 1e-5f;

// -------- device scratch (static: no allocation allowed) --------
__device__ float    g_h[(size_t)Nn * Cc];        // projected features (51.2 MB)
__device__ float    g_asrc[Nn * Hh];
__device__ float    g_adst[Nn * Hh];
__device__ int      g_deg[Nn];
__device__ int      g_cursor[Nn];
__device__ int      g_rowstart[Nn + 1];
__device__ int      g_csr_src[ET];
__device__ float    g_csr_ea[ET];                // edge attr in CSR order (3.4 MB)
__device__ double   g_colsum[Cc];
__device__ double   g_colsq[Cc];
__device__ double   g_easum;
__device__ float    g_ecoef[Hh];                 // sum_c W_edge[h,c]*att_edge[h,c]
__device__ float    g_eamean;

__device__ __forceinline__ float lrelu(float v) {
    return v > 0.f ? v : NEG_SLOPE * v;
}

// packed f32x2 FMA (Blackwell): d = a*b + c elementwise on two packed floats
__device__ __forceinline__ unsigned long long fma2(unsigned long long a,
                                                   unsigned long long b,
                                                   unsigned long long c) {
    unsigned long long d;
    asm("fma.rn.f32x2 %0, %1, %2, %3;" : "=l"(d) : "l"(a), "l"(b), "l"(c));
    return d;
}
__device__ __forceinline__ float unpk_lo(unsigned long long p) {
    return __uint_as_float((unsigned)p);
}
__device__ __forceinline__ float unpk_hi(unsigned long long p) {
    return __uint_as_float((unsigned)(p >> 32));
}

// -------- L1: mean(edge_attr) partial sums --------
__global__ void k_easum(const float* __restrict__ ea) {
    __shared__ double sh[256];
    double s = 0.0;
    for (int i = blockIdx.x * blockDim.x + threadIdx.x; i < Ee;
         i += gridDim.x * blockDim.x)
        s += (double)ea[i];
    sh[threadIdx.x] = s;
    __syncthreads();
    for (int o = 128; o; o >>= 1) {
        if (threadIdx.x < o) sh[threadIdx.x] += sh[threadIdx.x + o];
        __syncthreads();
    }
    if (threadIdx.x == 0) atomicAdd(&g_easum, sh[0]);
}

// -------- L2: per-head edge coefficient + ea mean scalar --------
__global__ void k_ecoef(const float* __restrict__ W_edge,
                        const float* __restrict__ att_edge) {
    int j = threadIdx.x;   // 256 threads
    float p = W_edge[j] * att_edge[j];
    for (int off = 16; off; off >>= 1) p += __shfl_down_sync(0xffffffffu, p, off);
    if ((j & 31) == 0) g_ecoef[j >> 5] = p;
    if (j == 0) g_eamean = (float)(g_easum / (double)Ee);
}

// -------- L3: zero the small accumulators (fresh every call) --------
__global__ void k_zero() {
    int i = blockIdx.x * blockDim.x + threadIdx.x;
    if (i < Nn) { g_deg[i] = 0; g_cursor[i] = 0; }
    if (i < Cc) { g_colsum[i] = 0.0; g_colsq[i] = 0.0; }
    if (i == 0) g_easum = 0.0;   // reset for NEXT graph replay
}

// -------- L4 (PROFILED SLOT): register-tiled GEMM h = x @ W ---------------
// Block tile 128x64, 256 threads, thread tile 8 rows x 4 cols.
// Shared tiles store (k-even,k-odd) float2 pairs so FFMA2 operands are
// naturally packed: 6 LDS.128 feed 32 FFMA2 per k-pair.
// Fused epilogue: per-head a_src/a_dst via xor-shuffle over the 8 lanes
// covering each head's 32 columns.
__global__ void __launch_bounds__(256, 2) k_gemm(
    const float* __restrict__ x, const float* __restrict__ W,
    const float* __restrict__ att_src, const float* __restrict__ att_dst)
{
    __shared__ float2 Ast[8][128];   // [k-pair][row]  8 KB
    __shared__ float2 Bst[8][64];    // [k-pair][col]  4 KB

    const int tid  = threadIdx.x;
    const int tx   = tid & 15;       // column group (4 cols)
    const int ty   = tid >> 4;       // row group (4+4 rows)
    const int row0 = blockIdx.y * 128;
    const int col0 = blockIdx.x * 64;

    const float4* __restrict__ x4 = (const float4*)x;
    const float4* __restrict__ W4 = (const float4*)W;

    // global load indices (fixed per thread)
    const int arow = tid >> 2;       // 0..63
    const int aq   = tid & 3;        // float4 within 16-k chunk
    const int bk   = tid >> 4;       // k within tile 0..15
    const int bc   = tid & 15;       // float4 col within 64-col tile

    float4 av0, av1, bw;
    {
        int r0 = row0 + arow, r1 = r0 + 64;
        av0 = (r0 < Nn) ? x4[(size_t)r0 * 64 + aq] : make_float4(0.f,0.f,0.f,0.f);
        av1 = (r1 < Nn) ? x4[(size_t)r1 * 64 + aq] : make_float4(0.f,0.f,0.f,0.f);
        bw  = W4[(size_t)bk * 64 + (col0 >> 2) + bc];
    }

    unsigned long long acc2[8][4];
#pragma unroll
    for (int r = 0; r < 8; r++)
#pragma unroll
        for (int c = 0; c < 4; c++) acc2[r][c] = 0ull;

#pragma unroll 1
    for (int kt = 0; kt < 16; kt++) {
        __syncthreads();
        // stage A as k-pairs
        Ast[2*aq    ][arow     ] = make_float2(av0.x, av0.y);
        Ast[2*aq + 1][arow     ] = make_float2(av0.z, av0.w);
        Ast[2*aq    ][arow + 64] = make_float2(av1.x, av1.y);
        Ast[2*aq + 1][arow + 64] = make_float2(av1.z, av1.w);
        // stage B as k-pairs
        {
            int kp = bk >> 1, par = bk & 1;
            float* bp = (float*)&Bst[kp][bc * 4];
            bp[0 + par] = bw.x; bp[2 + par] = bw.y;
            bp[4 + par] = bw.z; bp[6 + par] = bw.w;
        }
        __syncthreads();
        if (kt + 1 < 16) {   // prefetch next tile during compute
            int r0 = row0 + arow, r1 = r0 + 64;
            int kq = (kt + 1) * 4 + aq;
            av0 = (r0 < Nn) ? x4[(size_t)r0 * 64 + kq] : make_float4(0.f,0.f,0.f,0.f);
            av1 = (r1 < Nn) ? x4[(size_t)r1 * 64 + kq] : make_float4(0.f,0.f,0.f,0.f);
            bw  = W4[(size_t)((kt + 1) * 16 + bk) * 64 + (col0 >> 2) + bc];
        }
#pragma unroll
        for (int kp = 0; kp < 8; kp++) {
            ulonglong2 uA = *(const ulonglong2*)&Ast[kp][ty * 4];
            ulonglong2 uB = *(const ulonglong2*)&Ast[kp][ty * 4 + 2];
            ulonglong2 uC = *(const ulonglong2*)&Ast[kp][64 + ty * 4];
            ulonglong2 uD = *(const ulonglong2*)&Ast[kp][64 + ty * 4 + 2];
            ulonglong2 v0 = *(const ulonglong2*)&Bst[kp][tx * 4];
            ulonglong2 v1 = *(const ulonglong2*)&Bst[kp][tx * 4 + 2];
            unsigned long long ar[8] = {uA.x, uA.y, uB.x, uB.y,
                                        uC.x, uC.y, uD.x, uD.y};
            unsigned long long bv[4] = {v0.x, v0.y, v1.x, v1.y};
#pragma unroll
            for (int r = 0; r < 8; r++)
#pragma unroll
                for (int c = 0; c < 4; c++)
                    acc2[r][c] = fma2(ar[r], bv[c], acc2[r][c]);
        }
    }

    // ---- epilogue: store h, fused per-head attention dots ----
    const float4 asv = *(const float4*)&att_src[col0 + tx * 4];
    const float4 adv = *(const float4*)&att_dst[col0 + tx * 4];
#pragma unroll
    for (int r = 0; r < 8; r++) {
        int row = row0 + ((r < 4) ? (ty * 4 + r) : (64 + ty * 4 + r - 4));
        float c0 = unpk_lo(acc2[r][0]) + unpk_hi(acc2[r][0]);
        float c1 = unpk_lo(acc2[r][1]) + unpk_hi(acc2[r][1]);
        float c2 = unpk_lo(acc2[r][2]) + unpk_hi(acc2[r][2]);
        float c3 = unpk_lo(acc2[r][3]) + unpk_hi(acc2[r][3]);
        if (row < Nn)
            *(float4*)&g_h[(size_t)row * Cc + col0 + tx * 4] =
                make_float4(c0, c1, c2, c3);
        float ps = c0*asv.x + c1*asv.y + c2*asv.z + c3*asv.w;
        float pd = c0*adv.x + c1*adv.y + c2*adv.z + c3*adv.w;
#pragma unroll
        for (int o = 1; o < 8; o <<= 1) {
            ps += __shfl_xor_sync(0xffffffffu, ps, o);
            pd += __shfl_xor_sync(0xffffffffu, pd, o);
        }
        if ((tx & 7) == 0 && row < Nn) {
            int head = (col0 >> 5) + (tx >> 3);
            g_asrc[row * Hh + head] = ps;
            g_adst[row * Hh + head] = pd;
        }
    }
}

// -------- L5: destination-degree histogram --------
__global__ void __launch_bounds__(256) k_hist(const int* __restrict__ ei) {
    int e = blockIdx.x * blockDim.x + threadIdx.x;
    if (e >= ET) return;
    int d = (e < Ee) ? ei[Ee + e] : e - Ee;
    atomicAdd(&g_deg[d], 1);
}

// -------- L6: exclusive scan of degrees (single block) --------
__global__ void __launch_bounds__(1024) k_scan() {
    __shared__ int sh[1024];
    const int CH = (Nn + 1023) / 1024;   // 49
    int t = threadIdx.x;
    int base = t * CH;
    int s = 0;
    for (int i = 0; i < CH; i++) {
        int idx = base + i;
        if (idx < Nn) s += g_deg[idx];
    }
    sh[t] = s;
    __syncthreads();
    for (int o = 1; o < 1024; o <<= 1) {
        int v = (t >= o) ? sh[t - o] : 0;
        __syncthreads();
        sh[t] += v;
        __syncthreads();
    }
    int run = (t == 0) ? 0 : sh[t - 1];
    for (int i = 0; i < CH; i++) {
        int idx = base + i;
        if (idx < Nn) { g_rowstart[idx] = run; run += g_deg[idx]; }
    }
    if (t == 1023) g_rowstart[Nn] = ET;
}

// -------- L7: scatter edges into CSR (src + edge attr only) --------
__global__ void __launch_bounds__(256) k_scatter(const int* __restrict__ ei,
                                                 const float* __restrict__ ea) {
    int e = blockIdx.x * blockDim.x + threadIdx.x;
    if (e >= ET) return;
    int s, d; float a;
    if (e < Ee) { s = ei[e]; d = ei[Ee + e]; a = ea[e]; }
    else        { s = d = e - Ee; a = g_eamean; }
    int pos = g_rowstart[d] + atomicAdd(&g_cursor[d], 1);
    g_csr_src[pos] = s;
    g_csr_ea[pos]  = a;
}

// -------- L8: warp-per-node softmax + aggregation, logits recomputed --------
__global__ void __launch_bounds__(256) k_agg(float* __restrict__ out) {
    int node = (blockIdx.x * 256 + threadIdx.x) >> 5;
    if (node >= Nn) return;
    int lane = threadIdx.x & 31;
    int beg = g_rowstart[node];
    int end = g_rowstart[node + 1];

    const int h8 = lane & 7;
    const float adst = g_adst[node * Hh + h8];
    const float ec   = g_ecoef[h8];

    // pass 1: per-head max over the segment (4 edges x 8 heads per step)
    float mx = -1e30f;
    for (int p = beg + (lane >> 3); p < end; p += 4) {
        int s = g_csr_src[p];
        float a = g_csr_ea[p];
        float v = lrelu(g_asrc[s * Hh + h8] + adst + a * ec);
        mx = fmaxf(mx, v);
    }
    mx = fmaxf(mx, __shfl_xor_sync(0xffffffffu, mx, 8));
    mx = fmaxf(mx, __shfl_xor_sync(0xffffffffu, mx, 16));
    // lanes 0..7 now hold the max for head==lane

    // pass 2: weighted accumulation; lane owns columns [lane*8, lane*8+8)
    const int head = lane >> 2;       // head of this lane's 8 columns
    float4 accA = make_float4(0.f, 0.f, 0.f, 0.f);
    float4 accB = make_float4(0.f, 0.f, 0.f, 0.f);
    float wsum = 0.f;

#pragma unroll 2
    for (int p = beg; p < end; p++) {
        int s = g_csr_src[p];         // broadcast load
        float w = 0.f;
        if (lane < 8) {
            float a = g_csr_ea[p];
            float l = lrelu(g_asrc[s * Hh + lane] + adst + a * ec);
            w = __expf(l - mx);
        }
        wsum += w;
        float wh = __shfl_sync(0xffffffffu, w, head);
        const float4* hr = (const float4*)&g_h[(size_t)s * Cc + lane * 8];
        float4 v0 = hr[0], v1 = hr[1];
        accA.x += wh * v0.x; accA.y += wh * v0.y;
        accA.z += wh * v0.z; accA.w += wh * v0.w;
        accB.x += wh * v1.x; accB.y += wh * v1.y;
        accB.z += wh * v1.z; accB.w += wh * v1.w;
    }

    float inv = 1.f / (wsum + 1e-16f);            // valid on lanes 0..7
    float invh = __shfl_sync(0xffffffffu, inv, head);
    accA.x *= invh; accA.y *= invh; accA.z *= invh; accA.w *= invh;
    accB.x *= invh; accB.y *= invh; accB.z *= invh; accB.w *= invh;

    float4* orow = (float4*)&out[(size_t)node * Cc + lane * 8];
    orow[0] = accA;
    orow[1] = accB;
}

// -------- L9: per-column BN statistics --------
__global__ void __launch_bounds__(256) k_stats(const float* __restrict__ out) {
    int c = threadIdx.x;
    int r0 = blockIdx.x * 128;
    int rend = min(r0 + 128, Nn);
    double s = 0.0, q = 0.0;
    for (int n = r0; n < rend; n++) {
        float v = out[(size_t)n * Cc + c];
        s += (double)v;
        q += (double)v * (double)v;
    }
    atomicAdd(&g_colsum[c], s);
    atomicAdd(&g_colsq[c], q);
}

// -------- L10: BatchNorm + ELU (bias cancels in BN) --------
__global__ void __launch_bounds__(256) k_final(float* __restrict__ out,
                                               const float* __restrict__ gamma,
                                               const float* __restrict__ beta) {
    int i = blockIdx.x * blockDim.x + threadIdx.x;
    if (i >= Nn * Cc) return;
    int c = i & (Cc - 1);
    float v = out[i];
    float mean = (float)(g_colsum[c] / (double)Nn);
    float var = (float)(g_colsq[c] / (double)Nn) - mean * mean;
    float y = (v - mean) * rsqrtf(var + BN_EPS) * gamma[c] + beta[c];
    out[i] = y > 0.f ? y : expm1f(y);
}

extern "C" void kernel_launch(void* const* d_in, const int* in_sizes, int n_in,
                              void* d_out, int out_size) {
    const float* x        = (const float*)d_in[0];
    const int*   ei       = (const int*)d_in[1];
    const float* ea       = (const float*)d_in[2];
    const float* W        = (const float*)d_in[3];
    const float* att_src  = (const float*)d_in[4];
    const float* att_dst  = (const float*)d_in[5];
    const float* W_edge   = (const float*)d_in[6];
    const float* att_edge = (const float*)d_in[7];
    // d_in[8] = bias : cancels exactly through BatchNorm mean subtraction
    const float* gamma    = (const float*)d_in[9];
    const float* beta     = (const float*)d_in[10];
    float* out = (float*)d_out;

    k_easum  <<<512, 256>>>(ea);                               // 1
    k_ecoef  <<<1, 256>>>(W_edge, att_edge);                   // 2
    k_zero   <<<(Nn + 255) / 256, 256>>>();                    // 3
    dim3 ggrid(4, (Nn + 127) / 128);
    k_gemm   <<<ggrid, 256>>>(x, W, att_src, att_dst);         // 4 <- profiled
    k_hist   <<<(ET + 255) / 256, 256>>>(ei);                  // 5
    k_scan   <<<1, 1024>>>();                                  // 6
    k_scatter<<<(ET + 255) / 256, 256>>>(ei, ea);              // 7
    k_agg    <<<(Nn * 32 + 255) / 256, 256>>>(out);            // 8
    k_stats  <<<(Nn + 127) / 128, 256>>>(out);                 // 9
    k_final  <<<(Nn * Cc + 255) / 256, 256>>>(out, gamma, beta); // 10
}

// round 5
// speedup vs baseline: 1.3465x; 1.0072x over previous
#include <cuda_runtime.h>
#include <math.h>

static constexpr int   Nn        = 50000;
static constexpr int   Ee        = 800000;
static constexpr int   ET        = Nn + Ee;       // edges + self loops
static constexpr int   Cc        = 256;           // HEADS*OUT_C
static constexpr int   Hh        = 8;
static constexpr float NEG_SLOPE = 0.2f;
static constexpr float BN_EPS    = 1e-5f;

// -------- device scratch (static: no allocation allowed) --------
__device__ float    g_h[(size_t)Nn * Cc];        // projected features (51.2 MB)
__device__ float    g_asrc[Nn * Hh];
__device__ float    g_adst[Nn * Hh];
__device__ int      g_deg[Nn];
__device__ int      g_cursor[Nn];
__device__ int      g_rowstart[Nn + 1];
__device__ int2     g_csr[ET];                   // (src, edge_attr bits), 6.8 MB
__device__ double   g_colsum[Cc];
__device__ double   g_colsq[Cc];
__device__ double   g_easum;
__device__ float    g_ecoef[Hh];                 // sum_c W_edge[h,c]*att_edge[h,c]
__device__ float    g_eamean;

__device__ __forceinline__ float lrelu(float v) {
    return v > 0.f ? v : NEG_SLOPE * v;
}

// packed f32x2 FMA (Blackwell)
__device__ __forceinline__ unsigned long long fma2(unsigned long long a,
                                                   unsigned long long b,
                                                   unsigned long long c) {
    unsigned long long d;
    asm("fma.rn.f32x2 %0, %1, %2, %3;" : "=l"(d) : "l"(a), "l"(b), "l"(c));
    return d;
}
__device__ __forceinline__ float unpk_lo(unsigned long long p) {
    return __uint_as_float((unsigned)p);
}
__device__ __forceinline__ float unpk_hi(unsigned long long p) {
    return __uint_as_float((unsigned)(p >> 32));
}

// -------- L1: mean(edge_attr) partial sums --------
__global__ void k_easum(const float* __restrict__ ea) {
    __shared__ double sh[256];
    double s = 0.0;
    for (int i = blockIdx.x * blockDim.x + threadIdx.x; i < Ee;
         i += gridDim.x * blockDim.x)
        s += (double)ea[i];
    sh[threadIdx.x] = s;
    __syncthreads();
    for (int o = 128; o; o >>= 1) {
        if (threadIdx.x < o) sh[threadIdx.x] += sh[threadIdx.x + o];
        __syncthreads();
    }
    if (threadIdx.x == 0) atomicAdd(&g_easum, sh[0]);
}

// -------- L2: per-head edge coefficient + ea mean scalar --------
__global__ void k_ecoef(const float* __restrict__ W_edge,
                        const float* __restrict__ att_edge) {
    int j = threadIdx.x;   // 256 threads
    float p = W_edge[j] * att_edge[j];
    for (int off = 16; off; off >>= 1) p += __shfl_down_sync(0xffffffffu, p, off);
    if ((j & 31) == 0) g_ecoef[j >> 5] = p;
    if (j == 0) g_eamean = (float)(g_easum / (double)Ee);
}

// -------- L3: zero the small accumulators (fresh every call) --------
__global__ void k_zero() {
    int i = blockIdx.x * blockDim.x + threadIdx.x;
    if (i < Nn) { g_deg[i] = 0; g_cursor[i] = 0; }
    if (i < Cc) { g_colsum[i] = 0.0; g_colsq[i] = 0.0; }
    if (i == 0) g_easum = 0.0;   // reset for NEXT graph replay
}

// -------- L4 (PROFILED SLOT): register-tiled GEMM h = x @ W ---------------
// Block tile 128x64, 256 threads, thread tile 8 rows x 4 cols, FFMA2 packed
// along k. Fused per-head a_src/a_dst epilogue.
__global__ void __launch_bounds__(256, 2) k_gemm(
    const float* __restrict__ x, const float* __restrict__ W,
    const float* __restrict__ att_src, const float* __restrict__ att_dst)
{
    __shared__ float2 Ast[8][128];   // [k-pair][row]  8 KB
    __shared__ float2 Bst[8][64];    // [k-pair][col]  4 KB

    const int tid  = threadIdx.x;
    const int tx   = tid & 15;       // column group (4 cols)
    const int ty   = tid >> 4;       // row group (4+4 rows)
    const int row0 = blockIdx.y * 128;
    const int col0 = blockIdx.x * 64;

    const float4* __restrict__ x4 = (const float4*)x;
    const float4* __restrict__ W4 = (const float4*)W;

    const int arow = tid >> 2;       // 0..63
    const int aq   = tid & 3;        // float4 within 16-k chunk
    const int bk   = tid >> 4;       // k within tile 0..15
    const int bc   = tid & 15;       // float4 col within 64-col tile

    float4 av0, av1, bw;
    {
        int r0 = row0 + arow, r1 = r0 + 64;
        av0 = (r0 < Nn) ? x4[(size_t)r0 * 64 + aq] : make_float4(0.f,0.f,0.f,0.f);
        av1 = (r1 < Nn) ? x4[(size_t)r1 * 64 + aq] : make_float4(0.f,0.f,0.f,0.f);
        bw  = W4[(size_t)bk * 64 + (col0 >> 2) + bc];
    }

    unsigned long long acc2[8][4];
#pragma unroll
    for (int r = 0; r < 8; r++)
#pragma unroll
        for (int c = 0; c < 4; c++) acc2[r][c] = 0ull;

#pragma unroll 1
    for (int kt = 0; kt < 16; kt++) {
        __syncthreads();
        Ast[2*aq    ][arow     ] = make_float2(av0.x, av0.y);
        Ast[2*aq + 1][arow     ] = make_float2(av0.z, av0.w);
        Ast[2*aq    ][arow + 64] = make_float2(av1.x, av1.y);
        Ast[2*aq + 1][arow + 64] = make_float2(av1.z, av1.w);
        {
            int kp = bk >> 1, par = bk & 1;
            float* bp = (float*)&Bst[kp][bc * 4];
            bp[0 + par] = bw.x; bp[2 + par] = bw.y;
            bp[4 + par] = bw.z; bp[6 + par] = bw.w;
        }
        __syncthreads();
        if (kt + 1 < 16) {
            int r0 = row0 + arow, r1 = r0 + 64;
            int kq = (kt + 1) * 4 + aq;
            av0 = (r0 < Nn) ? x4[(size_t)r0 * 64 + kq] : make_float4(0.f,0.f,0.f,0.f);
            av1 = (r1 < Nn) ? x4[(size_t)r1 * 64 + kq] : make_float4(0.f,0.f,0.f,0.f);
            bw  = W4[(size_t)((kt + 1) * 16 + bk) * 64 + (col0 >> 2) + bc];
        }
#pragma unroll
        for (int kp = 0; kp < 8; kp++) {
            ulonglong2 uA = *(const ulonglong2*)&Ast[kp][ty * 4];
            ulonglong2 uB = *(const ulonglong2*)&Ast[kp][ty * 4 + 2];
            ulonglong2 uC = *(const ulonglong2*)&Ast[kp][64 + ty * 4];
            ulonglong2 uD = *(const ulonglong2*)&Ast[kp][64 + ty * 4 + 2];
            ulonglong2 v0 = *(const ulonglong2*)&Bst[kp][tx * 4];
            ulonglong2 v1 = *(const ulonglong2*)&Bst[kp][tx * 4 + 2];
            unsigned long long ar[8] = {uA.x, uA.y, uB.x, uB.y,
                                        uC.x, uC.y, uD.x, uD.y};
            unsigned long long bv[4] = {v0.x, v0.y, v1.x, v1.y};
#pragma unroll
            for (int r = 0; r < 8; r++)
#pragma unroll
                for (int c = 0; c < 4; c++)
                    acc2[r][c] = fma2(ar[r], bv[c], acc2[r][c]);
        }
    }

    const float4 asv = *(const float4*)&att_src[col0 + tx * 4];
    const float4 adv = *(const float4*)&att_dst[col0 + tx * 4];
#pragma unroll
    for (int r = 0; r < 8; r++) {
        int row = row0 + ((r < 4) ? (ty * 4 + r) : (64 + ty * 4 + r - 4));
        float c0 = unpk_lo(acc2[r][0]) + unpk_hi(acc2[r][0]);
        float c1 = unpk_lo(acc2[r][1]) + unpk_hi(acc2[r][1]);
        float c2 = unpk_lo(acc2[r][2]) + unpk_hi(acc2[r][2]);
        float c3 = unpk_lo(acc2[r][3]) + unpk_hi(acc2[r][3]);
        if (row < Nn)
            *(float4*)&g_h[(size_t)row * Cc + col0 + tx * 4] =
                make_float4(c0, c1, c2, c3);
        float ps = c0*asv.x + c1*asv.y + c2*asv.z + c3*asv.w;
        float pd = c0*adv.x + c1*adv.y + c2*adv.z + c3*adv.w;
#pragma unroll
        for (int o = 1; o < 8; o <<= 1) {
            ps += __shfl_xor_sync(0xffffffffu, ps, o);
            pd += __shfl_xor_sync(0xffffffffu, pd, o);
        }
        if ((tx & 7) == 0 && row < Nn) {
            int head = (col0 >> 5) + (tx >> 3);
            g_asrc[row * Hh + head] = ps;
            g_adst[row * Hh + head] = pd;
        }
    }
}

// -------- L5: destination-degree histogram --------
__global__ void __launch_bounds__(256) k_hist(const int* __restrict__ ei) {
    int e = blockIdx.x * blockDim.x + threadIdx.x;
    if (e >= ET) return;
    int d = (e < Ee) ? ei[Ee + e] : e - Ee;
    atomicAdd(&g_deg[d], 1);
}

// -------- L6: exclusive scan of degrees (single block) --------
__global__ void __launch_bounds__(1024) k_scan() {
    __shared__ int sh[1024];
    const int CH = (Nn + 1023) / 1024;   // 49
    int t = threadIdx.x;
    int base = t * CH;
    int s = 0;
    for (int i = 0; i < CH; i++) {
        int idx = base + i;
        if (idx < Nn) s += g_deg[idx];
    }
    sh[t] = s;
    __syncthreads();
    for (int o = 1; o < 1024; o <<= 1) {
        int v = (t >= o) ? sh[t - o] : 0;
        __syncthreads();
        sh[t] += v;
        __syncthreads();
    }
    int run = (t == 0) ? 0 : sh[t - 1];
    for (int i = 0; i < CH; i++) {
        int idx = base + i;
        if (idx < Nn) { g_rowstart[idx] = run; run += g_deg[idx]; }
    }
    if (t == 1023) g_rowstart[Nn] = ET;
}

// -------- L7: scatter edges into CSR as packed (src, ea) pairs --------
__global__ void __launch_bounds__(256) k_scatter(const int* __restrict__ ei,
                                                 const float* __restrict__ ea) {
    int e = blockIdx.x * blockDim.x + threadIdx.x;
    if (e >= ET) return;
    int s, d; float a;
    if (e < Ee) { s = ei[e]; d = ei[Ee + e]; a = ea[e]; }
    else        { s = d = e - Ee; a = g_eamean; }
    int pos = g_rowstart[d] + atomicAdd(&g_cursor[d], 1);
    g_csr[pos] = make_int2(s, __float_as_int(a));
}

// -------- L8: warp-per-node softmax + aggregation (single sweep) --------
// No max pass: logits are O(10), exp() cannot overflow fp32; normalized
// ratios identical to the max-shifted form. Edge (src,ea) pairs loaded
// coalesced 32-at-a-time, h[src] gathered as two contiguous 512B spans.
__global__ void __launch_bounds__(256) k_agg(float* __restrict__ out) {
    int node = (blockIdx.x * 256 + threadIdx.x) >> 5;
    if (node >= Nn) return;
    const int lane = threadIdx.x & 31;
    const int beg = g_rowstart[node];
    const int end = g_rowstart[node + 1];

    float adst = 0.f, ec = 0.f;
    if (lane < 8) {
        adst = g_adst[node * Hh + lane];
        ec   = g_ecoef[lane];
    }

    const int hs0 = lane >> 3;          // head lane for cols [4*lane, ...)
    const int hs1 = 4 + (lane >> 3);    // head lane for cols [128+4*lane, ...)

    float4 accA = make_float4(0.f, 0.f, 0.f, 0.f);
    float4 accB = make_float4(0.f, 0.f, 0.f, 0.f);
    float wsum = 0.f;

    for (int base = beg; base < end; base += 32) {
        int cnt = end - base;
        if (cnt > 32) cnt = 32;
        int sl = 0; float al = 0.f;
        if (lane < cnt) {
            int2 se = g_csr[base + lane];      // coalesced LDG.64
            sl = se.x;
            al = __int_as_float(se.y);
        }
#pragma unroll 4
        for (int i = 0; i < cnt; i++) {
            int   s = __shfl_sync(0xffffffffu, sl, i);
            float a = __shfl_sync(0xffffffffu, al, i);
            float w = 0.f;
            if (lane < 8)
                w = __expf(lrelu(g_asrc[s * Hh + lane] + adst + a * ec));
            wsum += w;
            float wh0 = __shfl_sync(0xffffffffu, w, hs0);
            float wh1 = __shfl_sync(0xffffffffu, w, hs1);
            const float4* hp = (const float4*)&g_h[(size_t)s * Cc];
            float4 v0 = hp[lane];          // cols [4*lane, 4*lane+4)
            float4 v1 = hp[32 + lane];     // cols [128+4*lane, ...)
            accA.x += wh0 * v0.x; accA.y += wh0 * v0.y;
            accA.z += wh0 * v0.z; accA.w += wh0 * v0.w;
            accB.x += wh1 * v1.x; accB.y += wh1 * v1.y;
            accB.z += wh1 * v1.z; accB.w += wh1 * v1.w;
        }
    }

    float inv = 1.f / (wsum + 1e-16f);     // valid on lanes 0..7
    float i0 = __shfl_sync(0xffffffffu, inv, hs0);
    float i1 = __shfl_sync(0xffffffffu, inv, hs1);
    accA.x *= i0; accA.y *= i0; accA.z *= i0; accA.w *= i0;
    accB.x *= i1; accB.y *= i1; accB.z *= i1; accB.w *= i1;

    float4* orow = (float4*)&out[(size_t)node * Cc];
    orow[lane]      = accA;
    orow[32 + lane] = accB;
}

// -------- L9: per-column BN statistics --------
__global__ void __launch_bounds__(256) k_stats(const float* __restrict__ out) {
    int c = threadIdx.x;
    int r0 = blockIdx.x * 128;
    int rend = min(r0 + 128, Nn);
    double s = 0.0, q = 0.0;
    for (int n = r0; n < rend; n++) {
        float v = out[(size_t)n * Cc + c];
        s += (double)v;
        q += (double)v * (double)v;
    }
    atomicAdd(&g_colsum[c], s);
    atomicAdd(&g_colsq[c], q);
}

// -------- L10: BatchNorm + ELU (bias cancels in BN) --------
__global__ void __launch_bounds__(256) k_final(float* __restrict__ out,
                                               const float* __restrict__ gamma,
                                               const float* __restrict__ beta) {
    int i = blockIdx.x * blockDim.x + threadIdx.x;
    if (i >= Nn * Cc) return;
    int c = i & (Cc - 1);
    float v = out[i];
    float mean = (float)(g_colsum[c] / (double)Nn);
    float var = (float)(g_colsq[c] / (double)Nn) - mean * mean;
    float y = (v - mean) * rsqrtf(var + BN_EPS) * gamma[c] + beta[c];
    out[i] = y > 0.f ? y : expm1f(y);
}

extern "C" void kernel_launch(void* const* d_in, const int* in_sizes, int n_in,
                              void* d_out, int out_size) {
    const float* x        = (const float*)d_in[0];
    const int*   ei       = (const int*)d_in[1];
    const float* ea       = (const float*)d_in[2];
    const float* W        = (const float*)d_in[3];
    const float* att_src  = (const float*)d_in[4];
    const float* att_dst  = (const float*)d_in[5];
    const float* W_edge   = (const float*)d_in[6];
    const float* att_edge = (const float*)d_in[7];
    // d_in[8] = bias : cancels exactly through BatchNorm mean subtraction
    const float* gamma    = (const float*)d_in[9];
    const float* beta     = (const float*)d_in[10];
    float* out = (float*)d_out;

    k_easum  <<<512, 256>>>(ea);                               // 1
    k_ecoef  <<<1, 256>>>(W_edge, att_edge);                   // 2
    k_zero   <<<(Nn + 255) / 256, 256>>>();                    // 3
    dim3 ggrid(4, (Nn + 127) / 128);
    k_gemm   <<<ggrid, 256>>>(x, W, att_src, att_dst);         // 4 <- profiled
    k_hist   <<<(ET + 255) / 256, 256>>>(ei);                  // 5
    k_scan   <<<1, 1024>>>();                                  // 6
    k_scatter<<<(ET + 255) / 256, 256>>>(ei, ea);              // 7
    k_agg    <<<(Nn * 32 + 255) / 256, 256>>>(out);            // 8
    k_stats  <<<(Nn + 127) / 128, 256>>>(out);                 // 9
    k_final  <<<(Nn * Cc + 255) / 256, 256>>>(out, gamma, beta); // 10
}

// round 6
// speedup vs baseline: 2.8779x; 2.1374x over previous
#include <cuda_runtime.h>
#include <math.h>

static constexpr int   Nn        = 50000;
static constexpr int   Ee        = 800000;
static constexpr int   ET        = Nn + Ee;       // edges + self loops
static constexpr int   Cc        = 256;           // HEADS*OUT_C
static constexpr int   Hh        = 8;
static constexpr float NEG_SLOPE = 0.2f;
static constexpr float BN_EPS    = 1e-5f;

// -------- device scratch (static: no allocation allowed) --------
__device__ float    g_h[(size_t)Nn * Cc];        // projected features (51.2 MB)
__device__ float    g_asrc[Nn * Hh];
__device__ float    g_adst[Nn * Hh];
__device__ int      g_deg[Nn];
__device__ int      g_cursor[Nn];
__device__ int      g_rowstart[Nn + 1];
__device__ int2     g_csr[ET];                   // (src, edge_attr bits), 6.8 MB
__device__ double   g_colsum[Cc];
__device__ double   g_colsq[Cc];
__device__ float    g_scale[Cc];                 // BN fused scale
__device__ float    g_shift[Cc];                 // BN fused shift
__device__ double   g_easum;
__device__ float    g_ecoef[Hh];                 // sum_c W_edge[h,c]*att_edge[h,c]
__device__ float    g_eamean;

__device__ __forceinline__ float lrelu(float v) {
    return v > 0.f ? v : NEG_SLOPE * v;
}

// packed f32x2 FMA (Blackwell)
__device__ __forceinline__ unsigned long long fma2(unsigned long long a,
                                                   unsigned long long b,
                                                   unsigned long long c) {
    unsigned long long d;
    asm("fma.rn.f32x2 %0, %1, %2, %3;" : "=l"(d) : "l"(a), "l"(b), "l"(c));
    return d;
}
__device__ __forceinline__ float unpk_lo(unsigned long long p) {
    return __uint_as_float((unsigned)p);
}
__device__ __forceinline__ float unpk_hi(unsigned long long p) {
    return __uint_as_float((unsigned)(p >> 32));
}

// -------- L1: mean(edge_attr) partial sums --------
__global__ void k_easum(const float* __restrict__ ea) {
    __shared__ double sh[256];
    double s = 0.0;
    for (int i = blockIdx.x * blockDim.x + threadIdx.x; i < Ee;
         i += gridDim.x * blockDim.x)
        s += (double)ea[i];
    sh[threadIdx.x] = s;
    __syncthreads();
    for (int o = 128; o; o >>= 1) {
        if (threadIdx.x < o) sh[threadIdx.x] += sh[threadIdx.x + o];
        __syncthreads();
    }
    if (threadIdx.x == 0) atomicAdd(&g_easum, sh[0]);
}

// -------- L2: per-head edge coefficient + ea mean scalar --------
__global__ void k_ecoef(const float* __restrict__ W_edge,
                        const float* __restrict__ att_edge) {
    int j = threadIdx.x;   // 256 threads
    float p = W_edge[j] * att_edge[j];
    for (int off = 16; off; off >>= 1) p += __shfl_down_sync(0xffffffffu, p, off);
    if ((j & 31) == 0) g_ecoef[j >> 5] = p;
    if (j == 0) g_eamean = (float)(g_easum / (double)Ee);
}

// -------- L3: zero the small accumulators (fresh every call) --------
__global__ void k_zero() {
    int i = blockIdx.x * blockDim.x + threadIdx.x;
    if (i < Nn) { g_deg[i] = 0; g_cursor[i] = 0; }
    if (i < Cc) { g_colsum[i] = 0.0; g_colsq[i] = 0.0; }
    if (i == 0) g_easum = 0.0;   // reset for NEXT graph replay
}

// -------- L4 (PROFILED SLOT): register-tiled GEMM h = x @ W ---------------
__global__ void __launch_bounds__(256, 2) k_gemm(
    const float* __restrict__ x, const float* __restrict__ W,
    const float* __restrict__ att_src, const float* __restrict__ att_dst)
{
    __shared__ float2 Ast[8][128];   // [k-pair][row]  8 KB
    __shared__ float2 Bst[8][64];    // [k-pair][col]  4 KB

    const int tid  = threadIdx.x;
    const int tx   = tid & 15;       // column group (4 cols)
    const int ty   = tid >> 4;       // row group (4+4 rows)
    const int row0 = blockIdx.y * 128;
    const int col0 = blockIdx.x * 64;

    const float4* __restrict__ x4 = (const float4*)x;
    const float4* __restrict__ W4 = (const float4*)W;

    const int arow = tid >> 2;       // 0..63
    const int aq   = tid & 3;        // float4 within 16-k chunk
    const int bk   = tid >> 4;       // k within tile 0..15
    const int bc   = tid & 15;       // float4 col within 64-col tile

    float4 av0, av1, bw;
    {
        int r0 = row0 + arow, r1 = r0 + 64;
        av0 = (r0 < Nn) ? x4[(size_t)r0 * 64 + aq] : make_float4(0.f,0.f,0.f,0.f);
        av1 = (r1 < Nn) ? x4[(size_t)r1 * 64 + aq] : make_float4(0.f,0.f,0.f,0.f);
        bw  = W4[(size_t)bk * 64 + (col0 >> 2) + bc];
    }

    unsigned long long acc2[8][4];
#pragma unroll
    for (int r = 0; r < 8; r++)
#pragma unroll
        for (int c = 0; c < 4; c++) acc2[r][c] = 0ull;

#pragma unroll 1
    for (int kt = 0; kt < 16; kt++) {
        __syncthreads();
        Ast[2*aq    ][arow     ] = make_float2(av0.x, av0.y);
        Ast[2*aq + 1][arow     ] = make_float2(av0.z, av0.w);
        Ast[2*aq    ][arow + 64] = make_float2(av1.x, av1.y);
        Ast[2*aq + 1][arow + 64] = make_float2(av1.z, av1.w);
        {
            int kp = bk >> 1, par = bk & 1;
            float* bp = (float*)&Bst[kp][bc * 4];
            bp[0 + par] = bw.x; bp[2 + par] = bw.y;
            bp[4 + par] = bw.z; bp[6 + par] = bw.w;
        }
        __syncthreads();
        if (kt + 1 < 16) {
            int r0 = row0 + arow, r1 = r0 + 64;
            int kq = (kt + 1) * 4 + aq;
            av0 = (r0 < Nn) ? x4[(size_t)r0 * 64 + kq] : make_float4(0.f,0.f,0.f,0.f);
            av1 = (r1 < Nn) ? x4[(size_t)r1 * 64 + kq] : make_float4(0.f,0.f,0.f,0.f);
            bw  = W4[(size_t)((kt + 1) * 16 + bk) * 64 + (col0 >> 2) + bc];
        }
#pragma unroll
        for (int kp = 0; kp < 8; kp++) {
            ulonglong2 uA = *(const ulonglong2*)&Ast[kp][ty * 4];
            ulonglong2 uB = *(const ulonglong2*)&Ast[kp][ty * 4 + 2];
            ulonglong2 uC = *(const ulonglong2*)&Ast[kp][64 + ty * 4];
            ulonglong2 uD = *(const ulonglong2*)&Ast[kp][64 + ty * 4 + 2];
            ulonglong2 v0 = *(const ulonglong2*)&Bst[kp][tx * 4];
            ulonglong2 v1 = *(const ulonglong2*)&Bst[kp][tx * 4 + 2];
            unsigned long long ar[8] = {uA.x, uA.y, uB.x, uB.y,
                                        uC.x, uC.y, uD.x, uD.y};
            unsigned long long bv[4] = {v0.x, v0.y, v1.x, v1.y};
#pragma unroll
            for (int r = 0; r < 8; r++)
#pragma unroll
                for (int c = 0; c < 4; c++)
                    acc2[r][c] = fma2(ar[r], bv[c], acc2[r][c]);
        }
    }

    const float4 asv = *(const float4*)&att_src[col0 + tx * 4];
    const float4 adv = *(const float4*)&att_dst[col0 + tx * 4];
#pragma unroll
    for (int r = 0; r < 8; r++) {
        int row = row0 + ((r < 4) ? (ty * 4 + r) : (64 + ty * 4 + r - 4));
        float c0 = unpk_lo(acc2[r][0]) + unpk_hi(acc2[r][0]);
        float c1 = unpk_lo(acc2[r][1]) + unpk_hi(acc2[r][1]);
        float c2 = unpk_lo(acc2[r][2]) + unpk_hi(acc2[r][2]);
        float c3 = unpk_lo(acc2[r][3]) + unpk_hi(acc2[r][3]);
        if (row < Nn)
            *(float4*)&g_h[(size_t)row * Cc + col0 + tx * 4] =
                make_float4(c0, c1, c2, c3);
        float ps = c0*asv.x + c1*asv.y + c2*asv.z + c3*asv.w;
        float pd = c0*adv.x + c1*adv.y + c2*adv.z + c3*adv.w;
#pragma unroll
        for (int o = 1; o < 8; o <<= 1) {
            ps += __shfl_xor_sync(0xffffffffu, ps, o);
            pd += __shfl_xor_sync(0xffffffffu, pd, o);
        }
        if ((tx & 7) == 0 && row < Nn) {
            int head = (col0 >> 5) + (tx >> 3);
            g_asrc[row * Hh + head] = ps;
            g_adst[row * Hh + head] = pd;
        }
    }
}

// -------- L5: destination-degree histogram --------
__global__ void __launch_bounds__(256) k_hist(const int* __restrict__ ei) {
    int e = blockIdx.x * blockDim.x + threadIdx.x;
    if (e >= ET) return;
    int d = (e < Ee) ? ei[Ee + e] : e - Ee;
    atomicAdd(&g_deg[d], 1);
}

// -------- L6: exclusive scan of degrees (single block) --------
__global__ void __launch_bounds__(1024) k_scan() {
    __shared__ int sh[1024];
    const int CH = (Nn + 1023) / 1024;   // 49
    int t = threadIdx.x;
    int base = t * CH;
    int s = 0;
    for (int i = 0; i < CH; i++) {
        int idx = base + i;
        if (idx < Nn) s += g_deg[idx];
    }
    sh[t] = s;
    __syncthreads();
    for (int o = 1; o < 1024; o <<= 1) {
        int v = (t >= o) ? sh[t - o] : 0;
        __syncthreads();
        sh[t] += v;
        __syncthreads();
    }
    int run = (t == 0) ? 0 : sh[t - 1];
    for (int i = 0; i < CH; i++) {
        int idx = base + i;
        if (idx < Nn) { g_rowstart[idx] = run; run += g_deg[idx]; }
    }
    if (t == 1023) g_rowstart[Nn] = ET;
}

// -------- L7: scatter edges into CSR as packed (src, ea) pairs --------
__global__ void __launch_bounds__(256) k_scatter(const int* __restrict__ ei,
                                                 const float* __restrict__ ea) {
    int e = blockIdx.x * blockDim.x + threadIdx.x;
    if (e >= ET) return;
    int s, d; float a;
    if (e < Ee) { s = ei[e]; d = ei[Ee + e]; a = ea[e]; }
    else        { s = d = e - Ee; a = g_eamean; }
    int pos = g_rowstart[d] + atomicAdd(&g_cursor[d], 1);
    g_csr[pos] = make_int2(s, __float_as_int(a));
}

// -------- L8: warp-per-node softmax + aggregation (single sweep) --------
__global__ void __launch_bounds__(256) k_agg(float* __restrict__ out) {
    int node = (blockIdx.x * 256 + threadIdx.x) >> 5;
    if (node >= Nn) return;
    const int lane = threadIdx.x & 31;
    const int beg = g_rowstart[node];
    const int end = g_rowstart[node + 1];

    float adst = 0.f, ec = 0.f;
    if (lane < 8) {
        adst = g_adst[node * Hh + lane];
        ec   = g_ecoef[lane];
    }

    const int hs0 = lane >> 3;          // head lane for cols [4*lane, ...)
    const int hs1 = 4 + (lane >> 3);    // head lane for cols [128+4*lane, ...)

    float4 accA = make_float4(0.f, 0.f, 0.f, 0.f);
    float4 accB = make_float4(0.f, 0.f, 0.f, 0.f);
    float wsum = 0.f;

    for (int base = beg; base < end; base += 32) {
        int cnt = end - base;
        if (cnt > 32) cnt = 32;
        int sl = 0; float al = 0.f;
        if (lane < cnt) {
            int2 se = g_csr[base + lane];      // coalesced LDG.64
            sl = se.x;
            al = __int_as_float(se.y);
        }
#pragma unroll 4
        for (int i = 0; i < cnt; i++) {
            int   s = __shfl_sync(0xffffffffu, sl, i);
            float a = __shfl_sync(0xffffffffu, al, i);
            float w = 0.f;
            if (lane < 8)
                w = __expf(lrelu(g_asrc[s * Hh + lane] + adst + a * ec));
            wsum += w;
            float wh0 = __shfl_sync(0xffffffffu, w, hs0);
            float wh1 = __shfl_sync(0xffffffffu, w, hs1);
            const float4* hp = (const float4*)&g_h[(size_t)s * Cc];
            float4 v0 = hp[lane];
            float4 v1 = hp[32 + lane];
            accA.x += wh0 * v0.x; accA.y += wh0 * v0.y;
            accA.z += wh0 * v0.z; accA.w += wh0 * v0.w;
            accB.x += wh1 * v1.x; accB.y += wh1 * v1.y;
            accB.z += wh1 * v1.z; accB.w += wh1 * v1.w;
        }
    }

    float inv = 1.f / (wsum + 1e-16f);     // valid on lanes 0..7
    float i0 = __shfl_sync(0xffffffffu, inv, hs0);
    float i1 = __shfl_sync(0xffffffffu, inv, hs1);
    accA.x *= i0; accA.y *= i0; accA.z *= i0; accA.w *= i0;
    accB.x *= i1; accB.y *= i1; accB.z *= i1; accB.w *= i1;

    float4* orow = (float4*)&out[(size_t)node * Cc];
    orow[lane]      = accA;
    orow[32 + lane] = accB;
}

// -------- L9: per-column BN statistics (fp32 inner, DP only at reduction) --
__global__ void __launch_bounds__(256) k_stats(const float* __restrict__ out) {
    int c = threadIdx.x;
    int r0 = blockIdx.x * 128;
    int rend = min(r0 + 128, Nn);
    float s = 0.f, q = 0.f;
    for (int n = r0; n < rend; n++) {
        float v = out[(size_t)n * Cc + c];
        s += v;
        q = fmaf(v, v, q);
    }
    atomicAdd(&g_colsum[c], (double)s);
    atomicAdd(&g_colsq[c], (double)q);
}

// -------- L10: fold BN into per-column scale/shift (all DP lives here) -----
__global__ void k_bnparam(const float* __restrict__ gamma,
                          const float* __restrict__ beta) {
    int c = threadIdx.x;   // 256 threads, 1 block
    double mean = g_colsum[c] / (double)Nn;
    double var  = g_colsq[c] / (double)Nn - mean * mean;
    float sc = (float)(rsqrt(var + (double)BN_EPS)) * gamma[c];
    g_scale[c] = sc;
    g_shift[c] = beta[c] - (float)mean * sc;
}

// -------- L11: BN apply + ELU, pure fp32 streaming --------
__global__ void __launch_bounds__(256) k_final(float* __restrict__ out) {
    int i = blockIdx.x * blockDim.x + threadIdx.x;
    if (i >= Nn * Cc / 4) return;
    int c4 = (i & 63) * 4;               // column of the float4
    float4 v = ((float4*)out)[i];
    float4 sc = *(const float4*)&g_scale[c4];
    float4 sh = *(const float4*)&g_shift[c4];
    v.x = fmaf(v.x, sc.x, sh.x);
    v.y = fmaf(v.y, sc.y, sh.y);
    v.z = fmaf(v.z, sc.z, sh.z);
    v.w = fmaf(v.w, sc.w, sh.w);
    v.x = v.x > 0.f ? v.x : expm1f(v.x);
    v.y = v.y > 0.f ? v.y : expm1f(v.y);
    v.z = v.z > 0.f ? v.z : expm1f(v.z);
    v.w = v.w > 0.f ? v.w : expm1f(v.w);
    ((float4*)out)[i] = v;
}

extern "C" void kernel_launch(void* const* d_in, const int* in_sizes, int n_in,
                              void* d_out, int out_size) {
    const float* x        = (const float*)d_in[0];
    const int*   ei       = (const int*)d_in[1];
    const float* ea       = (const float*)d_in[2];
    const float* W        = (const float*)d_in[3];
    const float* att_src  = (const float*)d_in[4];
    const float* att_dst  = (const float*)d_in[5];
    const float* W_edge   = (const float*)d_in[6];
    const float* att_edge = (const float*)d_in[7];
    // d_in[8] = bias : cancels exactly through BatchNorm mean subtraction
    const float* gamma    = (const float*)d_in[9];
    const float* beta     = (const float*)d_in[10];
    float* out = (float*)d_out;

    k_easum  <<<512, 256>>>(ea);                               // 1
    k_ecoef  <<<1, 256>>>(W_edge, att_edge);                   // 2
    k_zero   <<<(Nn + 255) / 256, 256>>>();                    // 3
    dim3 ggrid(4, (Nn + 127) / 128);
    k_gemm   <<<ggrid, 256>>>(x, W, att_src, att_dst);         // 4 <- profiled
    k_hist   <<<(ET + 255) / 256, 256>>>(ei);                  // 5
    k_scan   <<<1, 1024>>>();                                  // 6
    k_scatter<<<(ET + 255) / 256, 256>>>(ei, ea);              // 7
    k_agg    <<<(Nn * 32 + 255) / 256, 256>>>(out);            // 8
    k_stats  <<<(Nn + 127) / 128, 256>>>(out);                 // 9
    k_bnparam<<<1, 256>>>(gamma, beta);                        // 10
    k_final  <<<(Nn * Cc / 4 + 255) / 256, 256>>>(out);        // 11
}